// round 10
// baseline (speedup 1.0000x reference)
#include <cuda_runtime.h>
#include <cuda_fp16.h>

#define N_NODES 100000
#define MAX_E   1600000
#define D 64
#define SCAN_B 1024

struct Edge { int s; float nrm; };

// Scratch (allocation-free rule).
__device__ __align__(256) __half g_hh[N_NODES * D];   // fp16 gemm output (gather source)
__device__ __align__(256) float  g_t0[N_NODES * D];
__device__ __align__(256) float  g_t1[N_NODES * D];
__device__ int   g_deg [N_NODES];
__device__ int   g_fill[N_NODES];
__device__ int   g_rowp[N_NODES];
__device__ float g_dinv[N_NODES];
__device__ int   g_bsum[256];
__device__ __align__(8) Edge g_csr[MAX_E];

__global__ void k_zero(int n) {
    int i = blockIdx.x * blockDim.x + threadIdx.x;
    if (i < n) { g_deg[i] = 0; g_fill[i] = 0; }
}

__global__ void k_count_deg(const int* __restrict__ dst, int e) {
    int i = blockIdx.x * blockDim.x + threadIdx.x;
    if (i < e) atomicAdd(&g_deg[dst[i]], 1);
}

__global__ void k_dinv(int n) {
    int i = blockIdx.x * blockDim.x + threadIdx.x;
    if (i < n) g_dinv[i] = rsqrtf((float)g_deg[i] + 1.0f);
}

// ---- exclusive scan of g_deg -> g_rowp ----
__global__ void k_scan_block(int n) {
    __shared__ int sm[SCAN_B];
    int t = threadIdx.x;
    int i = blockIdx.x * SCAN_B + t;
    int v = (i < n) ? g_deg[i] : 0;
    sm[t] = v;
    __syncthreads();
    #pragma unroll
    for (int off = 1; off < SCAN_B; off <<= 1) {
        int add = (t >= off) ? sm[t - off] : 0;
        __syncthreads();
        sm[t] += add;
        __syncthreads();
    }
    if (i < n) g_rowp[i] = sm[t] - v;
    if (t == SCAN_B - 1) g_bsum[blockIdx.x] = sm[t];
}

__global__ void k_scan_bsum(int nb) {
    if (nb > 256) nb = 256;
    int acc = 0;
    for (int b = 0; b < nb; b++) { int v = g_bsum[b]; g_bsum[b] = acc; acc += v; }
}

__global__ void k_scan_add(int n) {
    int i = blockIdx.x * blockDim.x + threadIdx.x;
    if (i < n) g_rowp[i] += g_bsum[i / SCAN_B];
}

__global__ void k_fill(const int* __restrict__ src, const int* __restrict__ dst, int e) {
    int i = blockIdx.x * blockDim.x + threadIdx.x;
    if (i >= e) return;
    int s = src[i], d = dst[i];
    int pos = g_rowp[d] + atomicAdd(&g_fill[d], 1);
    if (pos >= MAX_E) pos = MAX_E - 1;
    Edge ed; ed.s = s; ed.nrm = g_dinv[s] * g_dinv[d];
    g_csr[pos] = ed;
}

// GEMM only: H(fp16) = (RELU? relu(A):A) @ W
// 256 threads/block, 128 rows/block. Thread: 4 rows x 8 cols (32 acc regs).
template<bool RELU>
__global__ void __launch_bounds__(256, 4) k_gemm(
        const float* __restrict__ A, const float* __restrict__ W,
        __half* __restrict__ Hh, int n) {
    __shared__ float4 Ws[1024];   // 64x64 W
    int tid = threadIdx.x;
    const float4* W4 = (const float4*)W;
    #pragma unroll
    for (int i = 0; i < 4; i++) Ws[tid + i * 256] = W4[tid + i * 256];
    __syncthreads();

    int cslice = tid & 7;                       // 8 col-slices of 8 cols
    int row0   = blockIdx.x * 128 + (tid >> 3) * 4;
    int c2     = cslice * 2;                    // first float4-col index

    const float4* Ar[4];
    #pragma unroll
    for (int rr = 0; rr < 4; rr++) {
        int r = row0 + rr; if (r >= n) r = n - 1;
        Ar[rr] = (const float4*)A + (size_t)r * 16;
    }

    float acc[4][8];
    #pragma unroll
    for (int r = 0; r < 4; r++)
        #pragma unroll
        for (int c = 0; c < 8; c++) acc[r][c] = 0.0f;

    #pragma unroll
    for (int k4 = 0; k4 < 16; k4++) {
        float4 a[4];
        #pragma unroll
        for (int rr = 0; rr < 4; rr++) {
            a[rr] = Ar[rr][k4];
            if (RELU) {
                a[rr].x = fmaxf(a[rr].x, 0.0f); a[rr].y = fmaxf(a[rr].y, 0.0f);
                a[rr].z = fmaxf(a[rr].z, 0.0f); a[rr].w = fmaxf(a[rr].w, 0.0f);
            }
        }
        #pragma unroll
        for (int j = 0; j < 4; j++) {
            int k = k4 * 4 + j;
            float4 w0 = Ws[k * 16 + c2];
            float4 w1 = Ws[k * 16 + c2 + 1];
            #pragma unroll
            for (int rr = 0; rr < 4; rr++) {
                float av = (&a[rr].x)[j];
                acc[rr][0] += av * w0.x; acc[rr][1] += av * w0.y;
                acc[rr][2] += av * w0.z; acc[rr][3] += av * w0.w;
                acc[rr][4] += av * w1.x; acc[rr][5] += av * w1.y;
                acc[rr][6] += av * w1.z; acc[rr][7] += av * w1.w;
            }
        }
    }

    #pragma unroll
    for (int rr = 0; rr < 4; rr++) {
        int r = row0 + rr;
        if (r >= n) break;
        __half2 p0 = __floats2half2_rn(acc[rr][0], acc[rr][1]);
        __half2 p1 = __floats2half2_rn(acc[rr][2], acc[rr][3]);
        __half2 p2 = __floats2half2_rn(acc[rr][4], acc[rr][5]);
        __half2 p3 = __floats2half2_rn(acc[rr][6], acc[rr][7]);
        uint4 hv;
        hv.x = reinterpret_cast<unsigned&>(p0);
        hv.y = reinterpret_cast<unsigned&>(p1);
        hv.z = reinterpret_cast<unsigned&>(p2);
        hv.w = reinterpret_cast<unsigned&>(p3);
        ((uint4*)Hh)[(size_t)r * 8 + cslice] = hv;
    }
}

// CSR gather + self-loop + bias (full GCNConv output, single cold write):
// out[node] = sum_e h[src_e]*nrm_e + h[node]*dinv^2 + b
// 8 lanes per dst node, lane l owns halves [l*8, l*8+8).
__global__ void __launch_bounds__(256) k_gather(const __half* __restrict__ Hh,
                                                const float* __restrict__ b,
                                                float* __restrict__ out, int n) {
    int t = blockIdx.x * blockDim.x + threadIdx.x;
    int node = t >> 3;
    if (node >= n) return;
    int l = t & 7;

    int start = __ldg(&g_rowp[node]);
    int cnt   = __ldg(&g_deg[node]);
    float di  = __ldg(&g_dinv[node]);
    const Edge* ce = g_csr + start;
    float acc[8];
    #pragma unroll
    for (int c = 0; c < 8; c++) acc[c] = 0.0f;

    if (cnt > 0) {
        Edge nxt = ce[0];
        for (int j = 0; j < cnt; j++) {
            Edge cur = nxt;
            if (j + 1 < cnt) nxt = ce[j + 1];
            uint4 hv = ((const uint4*)Hh)[(size_t)cur.s * 8 + l];
            __half2 p0 = reinterpret_cast<__half2&>(hv.x);
            __half2 p1 = reinterpret_cast<__half2&>(hv.y);
            __half2 p2 = reinterpret_cast<__half2&>(hv.z);
            __half2 p3 = reinterpret_cast<__half2&>(hv.w);
            float2 f0 = __half22float2(p0), f1 = __half22float2(p1);
            float2 f2 = __half22float2(p2), f3 = __half22float2(p3);
            float nm = cur.nrm;
            acc[0] += f0.x * nm; acc[1] += f0.y * nm;
            acc[2] += f1.x * nm; acc[3] += f1.y * nm;
            acc[4] += f2.x * nm; acc[5] += f2.y * nm;
            acc[6] += f3.x * nm; acc[7] += f3.y * nm;
        }
    }

    // self-loop term from own fp16 row + bias
    float s = di * di;
    uint4 hv = ((const uint4*)Hh)[(size_t)node * 8 + l];
    __half2 p0 = reinterpret_cast<__half2&>(hv.x);
    __half2 p1 = reinterpret_cast<__half2&>(hv.y);
    __half2 p2 = reinterpret_cast<__half2&>(hv.z);
    __half2 p3 = reinterpret_cast<__half2&>(hv.w);
    float2 f0 = __half22float2(p0), f1 = __half22float2(p1);
    float2 f2 = __half22float2(p2), f3 = __half22float2(p3);
    float4 b0 = __ldg((const float4*)b + l * 2);
    float4 b1 = __ldg((const float4*)b + l * 2 + 1);

    float4* o = (float4*)(out + (size_t)node * D + l * 8);
    o[0] = make_float4(acc[0] + f0.x * s + b0.x, acc[1] + f0.y * s + b0.y,
                       acc[2] + f1.x * s + b0.z, acc[3] + f1.y * s + b0.w);
    o[1] = make_float4(acc[4] + f2.x * s + b1.x, acc[5] + f2.y * s + b1.y,
                       acc[6] + f3.x * s + b1.z, acc[7] + f3.y * s + b1.w);
}

extern "C" void kernel_launch(void* const* d_in, const int* in_sizes, int n_in,
                              void* d_out, int out_size) {
    const float* x  = (const float*)d_in[0];
    const int*   ei = (const int*)d_in[1];   // int32 (JAX x64-disabled)
    const float* W0 = (const float*)d_in[2];
    const float* b0 = (const float*)d_in[3];
    const float* W1 = (const float*)d_in[4];
    const float* b1 = (const float*)d_in[5];
    const float* W2 = (const float*)d_in[6];
    const float* b2 = (const float*)d_in[7];
    float* out = (float*)d_out;

    int n = in_sizes[0] / D;
    int e = in_sizes[1] / 2;
    const int* src = ei;
    const int* dst = ei + e;

    __half* hh; float *t0, *t1;
    cudaGetSymbolAddress((void**)&hh, g_hh);
    cudaGetSymbolAddress((void**)&t0, g_t0);
    cudaGetSymbolAddress((void**)&t1, g_t1);

    const int TB = 256;
    int gb_n    = (n + TB - 1) / TB;
    int gb_e    = (e + TB - 1) / TB;
    int gb_gemm = (n + 127) / 128;
    int nb_scan = (n + SCAN_B - 1) / SCAN_B;
    long long nl = (long long)n * 8;
    int gb_ga   = (int)((nl + TB - 1) / TB);

    // CSR build (once per launch, reused by 3 layers)
    k_zero<<<gb_n, TB>>>(n);
    k_count_deg<<<gb_e, TB>>>(dst, e);
    k_dinv<<<gb_n, TB>>>(n);
    k_scan_block<<<nb_scan, SCAN_B>>>(n);
    k_scan_bsum<<<1, 1>>>(nb_scan);
    k_scan_add<<<gb_n, TB>>>(n);
    k_fill<<<gb_e, TB>>>(src, dst, e);

    // layer 0
    k_gemm<false><<<gb_gemm, TB>>>(x, W0, hh, n);
    k_gather<<<gb_ga, TB>>>(hh, b0, t0, n);
    // layer 1
    k_gemm<true><<<gb_gemm, TB>>>(t0, W1, hh, n);
    k_gather<<<gb_ga, TB>>>(hh, b1, t1, n);
    // layer 2
    k_gemm<true><<<gb_gemm, TB>>>(t1, W2, hh, n);
    k_gather<<<gb_ga, TB>>>(hh, b2, out, n);
}

// round 11
// speedup vs baseline: 1.0062x; 1.0062x over previous
#include <cuda_runtime.h>
#include <cuda_fp16.h>

#define N_NODES 100000
#define MAX_E   1600000
#define D 64
#define SCAN_B 1024

struct Edge { int s; float nrm; };

// Scratch (allocation-free rule).
__device__ __align__(256) __half g_hh[N_NODES * D];   // fp16 gemm output (gather source)
__device__ __align__(256) float  g_t0[N_NODES * D];
__device__ __align__(256) float  g_t1[N_NODES * D];
__device__ int   g_deg [N_NODES];
__device__ int   g_fill[N_NODES];
__device__ int   g_rowp[N_NODES];
__device__ float g_dinv[N_NODES];
__device__ int   g_bsum[256];
__device__ __align__(16) Edge g_csr[MAX_E];

__global__ void k_zero(int n) {
    int i = blockIdx.x * blockDim.x + threadIdx.x;
    if (i < n) { g_deg[i] = 0; g_fill[i] = 0; }
}

__global__ void k_count_deg(const int* __restrict__ dst, int e) {
    int i = blockIdx.x * blockDim.x + threadIdx.x;
    if (i < e) atomicAdd(&g_deg[dst[i]], 1);
}

// ---- exclusive scan of g_deg -> g_rowp ; also computes dinv (fused) ----
__global__ void k_scan_block(int n) {
    __shared__ int sm[SCAN_B];
    int t = threadIdx.x;
    int i = blockIdx.x * SCAN_B + t;
    int v = (i < n) ? g_deg[i] : 0;
    if (i < n) g_dinv[i] = rsqrtf((float)v + 1.0f);
    sm[t] = v;
    __syncthreads();
    #pragma unroll
    for (int off = 1; off < SCAN_B; off <<= 1) {
        int add = (t >= off) ? sm[t - off] : 0;
        __syncthreads();
        sm[t] += add;
        __syncthreads();
    }
    if (i < n) g_rowp[i] = sm[t] - v;
    if (t == SCAN_B - 1) g_bsum[blockIdx.x] = sm[t];
}

__global__ void k_scan_bsum(int nb) {
    if (nb > 256) nb = 256;
    int acc = 0;
    for (int b = 0; b < nb; b++) { int v = g_bsum[b]; g_bsum[b] = acc; acc += v; }
}

__global__ void k_scan_add(int n) {
    int i = blockIdx.x * blockDim.x + threadIdx.x;
    if (i < n) g_rowp[i] += g_bsum[i / SCAN_B];
}

__global__ void k_fill(const int* __restrict__ src, const int* __restrict__ dst, int e) {
    int i = blockIdx.x * blockDim.x + threadIdx.x;
    if (i >= e) return;
    int s = src[i], d = dst[i];
    int pos = g_rowp[d] + atomicAdd(&g_fill[d], 1);
    if (pos >= MAX_E) pos = MAX_E - 1;
    Edge ed; ed.s = s; ed.nrm = g_dinv[s] * g_dinv[d];
    g_csr[pos] = ed;
}

// GEMM only: H(fp16) = (RELU? relu(A):A) @ W
// 256 threads/block, 128 rows/block. Thread: 4 rows x 8 cols (32 acc regs).
template<bool RELU>
__global__ void __launch_bounds__(256, 4) k_gemm(
        const float* __restrict__ A, const float* __restrict__ W,
        __half* __restrict__ Hh, int n) {
    __shared__ float4 Ws[1024];   // 64x64 W
    int tid = threadIdx.x;
    const float4* W4 = (const float4*)W;
    #pragma unroll
    for (int i = 0; i < 4; i++) Ws[tid + i * 256] = W4[tid + i * 256];
    __syncthreads();

    int cslice = tid & 7;                       // 8 col-slices of 8 cols
    int row0   = blockIdx.x * 128 + (tid >> 3) * 4;
    int c2     = cslice * 2;                    // first float4-col index

    const float4* Ar[4];
    #pragma unroll
    for (int rr = 0; rr < 4; rr++) {
        int r = row0 + rr; if (r >= n) r = n - 1;
        Ar[rr] = (const float4*)A + (size_t)r * 16;
    }

    float acc[4][8];
    #pragma unroll
    for (int r = 0; r < 4; r++)
        #pragma unroll
        for (int c = 0; c < 8; c++) acc[r][c] = 0.0f;

    #pragma unroll
    for (int k4 = 0; k4 < 16; k4++) {
        float4 a[4];
        #pragma unroll
        for (int rr = 0; rr < 4; rr++) {
            a[rr] = Ar[rr][k4];
            if (RELU) {
                a[rr].x = fmaxf(a[rr].x, 0.0f); a[rr].y = fmaxf(a[rr].y, 0.0f);
                a[rr].z = fmaxf(a[rr].z, 0.0f); a[rr].w = fmaxf(a[rr].w, 0.0f);
            }
        }
        #pragma unroll
        for (int j = 0; j < 4; j++) {
            int k = k4 * 4 + j;
            float4 w0 = Ws[k * 16 + c2];
            float4 w1 = Ws[k * 16 + c2 + 1];
            #pragma unroll
            for (int rr = 0; rr < 4; rr++) {
                float av = (&a[rr].x)[j];
                acc[rr][0] += av * w0.x; acc[rr][1] += av * w0.y;
                acc[rr][2] += av * w0.z; acc[rr][3] += av * w0.w;
                acc[rr][4] += av * w1.x; acc[rr][5] += av * w1.y;
                acc[rr][6] += av * w1.z; acc[rr][7] += av * w1.w;
            }
        }
    }

    #pragma unroll
    for (int rr = 0; rr < 4; rr++) {
        int r = row0 + rr;
        if (r >= n) break;
        __half2 p0 = __floats2half2_rn(acc[rr][0], acc[rr][1]);
        __half2 p1 = __floats2half2_rn(acc[rr][2], acc[rr][3]);
        __half2 p2 = __floats2half2_rn(acc[rr][4], acc[rr][5]);
        __half2 p3 = __floats2half2_rn(acc[rr][6], acc[rr][7]);
        uint4 hv;
        hv.x = reinterpret_cast<unsigned&>(p0);
        hv.y = reinterpret_cast<unsigned&>(p1);
        hv.z = reinterpret_cast<unsigned&>(p2);
        hv.w = reinterpret_cast<unsigned&>(p3);
        ((uint4*)Hh)[(size_t)r * 8 + cslice] = hv;
    }
}

// CSR gather + self-loop + bias, 4x unrolled for MLP.
// out[node] = sum_e h[src_e]*nrm_e + h[node]*dinv^2 + b
// 8 lanes per dst node, lane l owns halves [l*8, l*8+8).
__global__ void __launch_bounds__(256) k_gather(const __half* __restrict__ Hh,
                                                const float* __restrict__ b,
                                                float* __restrict__ out, int n) {
    int t = blockIdx.x * blockDim.x + threadIdx.x;
    int node = t >> 3;
    if (node >= n) return;
    int l = t & 7;

    int start = __ldg(&g_rowp[node]);
    int cnt   = __ldg(&g_deg[node]);
    float di  = __ldg(&g_dinv[node]);
    const Edge* ce = g_csr + start;
    const uint4* H4 = (const uint4*)Hh;

    float acc[8];
    #pragma unroll
    for (int c = 0; c < 8; c++) acc[c] = 0.0f;

    int j = 0;
    // 4-wide unroll: 4 independent edge loads + 4 independent H loads -> MLP >= 4
    for (; j + 4 <= cnt; j += 4) {
        Edge e0 = ce[j], e1 = ce[j+1], e2 = ce[j+2], e3 = ce[j+3];
        uint4 h0 = H4[(size_t)e0.s * 8 + l];
        uint4 h1 = H4[(size_t)e1.s * 8 + l];
        uint4 h2 = H4[(size_t)e2.s * 8 + l];
        uint4 h3 = H4[(size_t)e3.s * 8 + l];
        const uint4* hv[4] = {&h0, &h1, &h2, &h3};
        float nm[4] = {e0.nrm, e1.nrm, e2.nrm, e3.nrm};
        #pragma unroll
        for (int q = 0; q < 4; q++) {
            __half2 p0 = reinterpret_cast<const __half2&>(hv[q]->x);
            __half2 p1 = reinterpret_cast<const __half2&>(hv[q]->y);
            __half2 p2 = reinterpret_cast<const __half2&>(hv[q]->z);
            __half2 p3 = reinterpret_cast<const __half2&>(hv[q]->w);
            float2 f0 = __half22float2(p0), f1 = __half22float2(p1);
            float2 f2 = __half22float2(p2), f3 = __half22float2(p3);
            acc[0] += f0.x * nm[q]; acc[1] += f0.y * nm[q];
            acc[2] += f1.x * nm[q]; acc[3] += f1.y * nm[q];
            acc[4] += f2.x * nm[q]; acc[5] += f2.y * nm[q];
            acc[6] += f3.x * nm[q]; acc[7] += f3.y * nm[q];
        }
    }
    for (; j < cnt; j++) {
        Edge cur = ce[j];
        uint4 hv = H4[(size_t)cur.s * 8 + l];
        __half2 p0 = reinterpret_cast<__half2&>(hv.x);
        __half2 p1 = reinterpret_cast<__half2&>(hv.y);
        __half2 p2 = reinterpret_cast<__half2&>(hv.z);
        __half2 p3 = reinterpret_cast<__half2&>(hv.w);
        float2 f0 = __half22float2(p0), f1 = __half22float2(p1);
        float2 f2 = __half22float2(p2), f3 = __half22float2(p3);
        float nm = cur.nrm;
        acc[0] += f0.x * nm; acc[1] += f0.y * nm;
        acc[2] += f1.x * nm; acc[3] += f1.y * nm;
        acc[4] += f2.x * nm; acc[5] += f2.y * nm;
        acc[6] += f3.x * nm; acc[7] += f3.y * nm;
    }

    // self-loop term from own fp16 row + bias
    float s = di * di;
    uint4 hv = H4[(size_t)node * 8 + l];
    __half2 p0 = reinterpret_cast<__half2&>(hv.x);
    __half2 p1 = reinterpret_cast<__half2&>(hv.y);
    __half2 p2 = reinterpret_cast<__half2&>(hv.z);
    __half2 p3 = reinterpret_cast<__half2&>(hv.w);
    float2 f0 = __half22float2(p0), f1 = __half22float2(p1);
    float2 f2 = __half22float2(p2), f3 = __half22float2(p3);
    float4 b0 = __ldg((const float4*)b + l * 2);
    float4 b1 = __ldg((const float4*)b + l * 2 + 1);

    float4* o = (float4*)(out + (size_t)node * D + l * 8);
    o[0] = make_float4(acc[0] + f0.x * s + b0.x, acc[1] + f0.y * s + b0.y,
                       acc[2] + f1.x * s + b0.z, acc[3] + f1.y * s + b0.w);
    o[1] = make_float4(acc[4] + f2.x * s + b1.x, acc[5] + f2.y * s + b1.y,
                       acc[6] + f3.x * s + b1.z, acc[7] + f3.y * s + b1.w);
}

extern "C" void kernel_launch(void* const* d_in, const int* in_sizes, int n_in,
                              void* d_out, int out_size) {
    const float* x  = (const float*)d_in[0];
    const int*   ei = (const int*)d_in[1];   // int32 (JAX x64-disabled)
    const float* W0 = (const float*)d_in[2];
    const float* b0 = (const float*)d_in[3];
    const float* W1 = (const float*)d_in[4];
    const float* b1 = (const float*)d_in[5];
    const float* W2 = (const float*)d_in[6];
    const float* b2 = (const float*)d_in[7];
    float* out = (float*)d_out;

    int n = in_sizes[0] / D;
    int e = in_sizes[1] / 2;
    const int* src = ei;
    const int* dst = ei + e;

    __half* hh; float *t0, *t1;
    cudaGetSymbolAddress((void**)&hh, g_hh);
    cudaGetSymbolAddress((void**)&t0, g_t0);
    cudaGetSymbolAddress((void**)&t1, g_t1);

    const int TB = 256;
    int gb_n    = (n + TB - 1) / TB;
    int gb_e    = (e + TB - 1) / TB;
    int gb_gemm = (n + 127) / 128;
    int nb_scan = (n + SCAN_B - 1) / SCAN_B;
    long long nl = (long long)n * 8;
    int gb_ga   = (int)((nl + TB - 1) / TB);

    // Launch order puts gemm0 at index 3 (the launch ncu captures).
    k_zero<<<gb_n, TB>>>(n);                          // 0
    k_count_deg<<<gb_e, TB>>>(dst, e);                // 1
    k_scan_block<<<nb_scan, SCAN_B>>>(n);             // 2 (also computes dinv)
    k_gemm<false><<<gb_gemm, TB>>>(x, W0, hh, n);     // 3  <- profiled
    k_scan_bsum<<<1, 1>>>(nb_scan);                   // 4
    k_scan_add<<<gb_n, TB>>>(n);                      // 5
    k_fill<<<gb_e, TB>>>(src, dst, e);                // 6
    // layer 0 aggregate
    k_gather<<<gb_ga, TB>>>(hh, b0, t0, n);           // 7
    // layer 1
    k_gemm<true><<<gb_gemm, TB>>>(t0, W1, hh, n);
    k_gather<<<gb_ga, TB>>>(hh, b1, t1, n);
    // layer 2
    k_gemm<true><<<gb_gemm, TB>>>(t1, W2, hh, n);
    k_gather<<<gb_ga, TB>>>(hh, b2, out, n);
}

// round 12
// speedup vs baseline: 1.1247x; 1.1178x over previous
#include <cuda_runtime.h>
#include <cuda_fp16.h>

#define N_NODES 100000
#define MAX_E   1600000
#define D 64
#define SCAN_B 1024

struct Edge { int s; float nrm; };

// Scratch (allocation-free rule).
__device__ __align__(256) __half g_hh[N_NODES * D];   // fp16 gemm output (gather source)
__device__ __align__(256) float  g_t0[N_NODES * D];
__device__ __align__(256) float  g_t1[N_NODES * D];
__device__ int   g_deg [N_NODES];
__device__ int   g_fill[N_NODES];
__device__ int   g_rowp[N_NODES];
__device__ float g_dinv[N_NODES];
__device__ int   g_bsum[256];
__device__ __align__(16) Edge g_csr[MAX_E];

__global__ void k_zero(int n) {
    int i = blockIdx.x * blockDim.x + threadIdx.x;
    if (i < n) { g_deg[i] = 0; g_fill[i] = 0; }
}

__global__ void k_count_deg(const int* __restrict__ dst, int e) {
    int i = blockIdx.x * blockDim.x + threadIdx.x;
    if (i < e) atomicAdd(&g_deg[dst[i]], 1);
}

// ---- exclusive scan of g_deg -> g_rowp ; also computes dinv (fused) ----
__global__ void k_scan_block(int n) {
    __shared__ int sm[SCAN_B];
    int t = threadIdx.x;
    int i = blockIdx.x * SCAN_B + t;
    int v = (i < n) ? g_deg[i] : 0;
    if (i < n) g_dinv[i] = rsqrtf((float)v + 1.0f);
    sm[t] = v;
    __syncthreads();
    #pragma unroll
    for (int off = 1; off < SCAN_B; off <<= 1) {
        int add = (t >= off) ? sm[t - off] : 0;
        __syncthreads();
        sm[t] += add;
        __syncthreads();
    }
    if (i < n) g_rowp[i] = sm[t] - v;
    if (t == SCAN_B - 1) g_bsum[blockIdx.x] = sm[t];
}

__global__ void k_scan_bsum(int nb) {
    if (nb > 256) nb = 256;
    int acc = 0;
    for (int b = 0; b < nb; b++) { int v = g_bsum[b]; g_bsum[b] = acc; acc += v; }
}

__global__ void k_scan_add(int n) {
    int i = blockIdx.x * blockDim.x + threadIdx.x;
    if (i < n) g_rowp[i] += g_bsum[i / SCAN_B];
}

__global__ void k_fill(const int* __restrict__ src, const int* __restrict__ dst, int e) {
    int i = blockIdx.x * blockDim.x + threadIdx.x;
    if (i >= e) return;
    int s = src[i], d = dst[i];
    int pos = g_rowp[d] + atomicAdd(&g_fill[d], 1);
    if (pos >= MAX_E) pos = MAX_E - 1;
    Edge ed; ed.s = s; ed.nrm = g_dinv[s] * g_dinv[d];
    g_csr[pos] = ed;
}

// GEMM: H(fp16) = (RELU? relu(A):A) @ W
// 256 threads/block, 256 rows/block. Thread: 8 rows x 8 cols (64 acc regs).
// Each LDS.128 of W now feeds 32 FFMAs (halved LDS traffic vs 4-row version).
template<bool RELU>
__global__ void __launch_bounds__(256, 2) k_gemm(
        const float* __restrict__ A, const float* __restrict__ W,
        __half* __restrict__ Hh, int n) {
    __shared__ float4 Ws[1024];   // 64x64 W
    int tid = threadIdx.x;
    const float4* W4 = (const float4*)W;
    #pragma unroll
    for (int i = 0; i < 4; i++) Ws[tid + i * 256] = W4[tid + i * 256];
    __syncthreads();

    int cslice = tid & 7;                         // 8 col-slices of 8 cols
    int row0   = blockIdx.x * 256 + (tid >> 3) * 8;
    int c2     = cslice * 2;                      // first float4-col index

    const float4* Ar[8];
    #pragma unroll
    for (int rr = 0; rr < 8; rr++) {
        int r = row0 + rr; if (r >= n) r = n - 1;
        Ar[rr] = (const float4*)A + (size_t)r * 16;
    }

    float acc[8][8];
    #pragma unroll
    for (int r = 0; r < 8; r++)
        #pragma unroll
        for (int c = 0; c < 8; c++) acc[r][c] = 0.0f;

    #pragma unroll
    for (int k4 = 0; k4 < 16; k4++) {
        float4 a[8];
        #pragma unroll
        for (int rr = 0; rr < 8; rr++) {
            a[rr] = Ar[rr][k4];
            if (RELU) {
                a[rr].x = fmaxf(a[rr].x, 0.0f); a[rr].y = fmaxf(a[rr].y, 0.0f);
                a[rr].z = fmaxf(a[rr].z, 0.0f); a[rr].w = fmaxf(a[rr].w, 0.0f);
            }
        }
        #pragma unroll
        for (int j = 0; j < 4; j++) {
            int k = k4 * 4 + j;
            float4 w0 = Ws[k * 16 + c2];
            float4 w1 = Ws[k * 16 + c2 + 1];
            #pragma unroll
            for (int rr = 0; rr < 8; rr++) {
                float av = (&a[rr].x)[j];
                acc[rr][0] += av * w0.x; acc[rr][1] += av * w0.y;
                acc[rr][2] += av * w0.z; acc[rr][3] += av * w0.w;
                acc[rr][4] += av * w1.x; acc[rr][5] += av * w1.y;
                acc[rr][6] += av * w1.z; acc[rr][7] += av * w1.w;
            }
        }
    }

    #pragma unroll
    for (int rr = 0; rr < 8; rr++) {
        int r = row0 + rr;
        if (r >= n) break;
        __half2 p0 = __floats2half2_rn(acc[rr][0], acc[rr][1]);
        __half2 p1 = __floats2half2_rn(acc[rr][2], acc[rr][3]);
        __half2 p2 = __floats2half2_rn(acc[rr][4], acc[rr][5]);
        __half2 p3 = __floats2half2_rn(acc[rr][6], acc[rr][7]);
        uint4 hv;
        hv.x = reinterpret_cast<unsigned&>(p0);
        hv.y = reinterpret_cast<unsigned&>(p1);
        hv.z = reinterpret_cast<unsigned&>(p2);
        hv.w = reinterpret_cast<unsigned&>(p3);
        ((uint4*)Hh)[(size_t)r * 8 + cslice] = hv;
    }
}

// CSR gather + self-loop + bias, 4x unrolled for MLP.
// out[node] = sum_e h[src_e]*nrm_e + h[node]*dinv^2 + b
// 8 lanes per dst node, lane l owns halves [l*8, l*8+8).
__global__ void __launch_bounds__(256) k_gather(const __half* __restrict__ Hh,
                                                const float* __restrict__ b,
                                                float* __restrict__ out, int n) {
    int t = blockIdx.x * blockDim.x + threadIdx.x;
    int node = t >> 3;
    if (node >= n) return;
    int l = t & 7;

    int start = __ldg(&g_rowp[node]);
    int cnt   = __ldg(&g_deg[node]);
    float di  = __ldg(&g_dinv[node]);
    const Edge* ce = g_csr + start;
    const uint4* H4 = (const uint4*)Hh;

    float acc[8];
    #pragma unroll
    for (int c = 0; c < 8; c++) acc[c] = 0.0f;

    int j = 0;
    for (; j + 4 <= cnt; j += 4) {
        Edge e0 = ce[j], e1 = ce[j+1], e2 = ce[j+2], e3 = ce[j+3];
        uint4 h0 = H4[(size_t)e0.s * 8 + l];
        uint4 h1 = H4[(size_t)e1.s * 8 + l];
        uint4 h2 = H4[(size_t)e2.s * 8 + l];
        uint4 h3 = H4[(size_t)e3.s * 8 + l];
        const uint4* hv[4] = {&h0, &h1, &h2, &h3};
        float nm[4] = {e0.nrm, e1.nrm, e2.nrm, e3.nrm};
        #pragma unroll
        for (int q = 0; q < 4; q++) {
            __half2 p0 = reinterpret_cast<const __half2&>(hv[q]->x);
            __half2 p1 = reinterpret_cast<const __half2&>(hv[q]->y);
            __half2 p2 = reinterpret_cast<const __half2&>(hv[q]->z);
            __half2 p3 = reinterpret_cast<const __half2&>(hv[q]->w);
            float2 f0 = __half22float2(p0), f1 = __half22float2(p1);
            float2 f2 = __half22float2(p2), f3 = __half22float2(p3);
            acc[0] += f0.x * nm[q]; acc[1] += f0.y * nm[q];
            acc[2] += f1.x * nm[q]; acc[3] += f1.y * nm[q];
            acc[4] += f2.x * nm[q]; acc[5] += f2.y * nm[q];
            acc[6] += f3.x * nm[q]; acc[7] += f3.y * nm[q];
        }
    }
    for (; j < cnt; j++) {
        Edge cur = ce[j];
        uint4 hv = H4[(size_t)cur.s * 8 + l];
        __half2 p0 = reinterpret_cast<__half2&>(hv.x);
        __half2 p1 = reinterpret_cast<__half2&>(hv.y);
        __half2 p2 = reinterpret_cast<__half2&>(hv.z);
        __half2 p3 = reinterpret_cast<__half2&>(hv.w);
        float2 f0 = __half22float2(p0), f1 = __half22float2(p1);
        float2 f2 = __half22float2(p2), f3 = __half22float2(p3);
        float nm = cur.nrm;
        acc[0] += f0.x * nm; acc[1] += f0.y * nm;
        acc[2] += f1.x * nm; acc[3] += f1.y * nm;
        acc[4] += f2.x * nm; acc[5] += f2.y * nm;
        acc[6] += f3.x * nm; acc[7] += f3.y * nm;
    }

    float s = di * di;
    uint4 hv = H4[(size_t)node * 8 + l];
    __half2 p0 = reinterpret_cast<__half2&>(hv.x);
    __half2 p1 = reinterpret_cast<__half2&>(hv.y);
    __half2 p2 = reinterpret_cast<__half2&>(hv.z);
    __half2 p3 = reinterpret_cast<__half2&>(hv.w);
    float2 f0 = __half22float2(p0), f1 = __half22float2(p1);
    float2 f2 = __half22float2(p2), f3 = __half22float2(p3);
    float4 b0 = __ldg((const float4*)b + l * 2);
    float4 b1 = __ldg((const float4*)b + l * 2 + 1);

    float4* o = (float4*)(out + (size_t)node * D + l * 8);
    o[0] = make_float4(acc[0] + f0.x * s + b0.x, acc[1] + f0.y * s + b0.y,
                       acc[2] + f1.x * s + b0.z, acc[3] + f1.y * s + b0.w);
    o[1] = make_float4(acc[4] + f2.x * s + b1.x, acc[5] + f2.y * s + b1.y,
                       acc[6] + f3.x * s + b1.z, acc[7] + f3.y * s + b1.w);
}

extern "C" void kernel_launch(void* const* d_in, const int* in_sizes, int n_in,
                              void* d_out, int out_size) {
    const float* x  = (const float*)d_in[0];
    const int*   ei = (const int*)d_in[1];   // int32 (JAX x64-disabled)
    const float* W0 = (const float*)d_in[2];
    const float* b0 = (const float*)d_in[3];
    const float* W1 = (const float*)d_in[4];
    const float* b1 = (const float*)d_in[5];
    const float* W2 = (const float*)d_in[6];
    const float* b2 = (const float*)d_in[7];
    float* out = (float*)d_out;

    int n = in_sizes[0] / D;
    int e = in_sizes[1] / 2;
    const int* src = ei;
    const int* dst = ei + e;

    __half* hh; float *t0, *t1;
    cudaGetSymbolAddress((void**)&hh, g_hh);
    cudaGetSymbolAddress((void**)&t0, g_t0);
    cudaGetSymbolAddress((void**)&t1, g_t1);

    const int TB = 256;
    int gb_n    = (n + TB - 1) / TB;
    int gb_e    = (e + TB - 1) / TB;
    int gb_gemm = (n + 255) / 256;
    int nb_scan = (n + SCAN_B - 1) / SCAN_B;
    long long nl = (long long)n * 8;
    int gb_ga   = (int)((nl + TB - 1) / TB);

    // Launch order puts gemm0 at index 3 (the launch ncu captures).
    k_zero<<<gb_n, TB>>>(n);                          // 0
    k_count_deg<<<gb_e, TB>>>(dst, e);                // 1
    k_scan_block<<<nb_scan, SCAN_B>>>(n);             // 2 (also computes dinv)
    k_gemm<false><<<gb_gemm, TB>>>(x, W0, hh, n);     // 3  <- profiled
    k_scan_bsum<<<1, 1>>>(nb_scan);                   // 4
    k_scan_add<<<gb_n, TB>>>(n);                      // 5
    k_fill<<<gb_e, TB>>>(src, dst, e);                // 6
    // layer 0 aggregate
    k_gather<<<gb_ga, TB>>>(hh, b0, t0, n);           // 7
    // layer 1
    k_gemm<true><<<gb_gemm, TB>>>(t0, W1, hh, n);
    k_gather<<<gb_ga, TB>>>(hh, b1, t1, n);
    // layer 2
    k_gemm<true><<<gb_gemm, TB>>>(t1, W2, hh, n);
    k_gather<<<gb_ga, TB>>>(hh, b2, out, n);
}